// round 1
// baseline (speedup 1.0000x reference)
#include <cuda_runtime.h>

// MC_Module_Batch: bilinear backward warp + weight + sum over R.
// Shapes: pred [B,R,C,H,W], mv [B,R,2,H,W] (quarter-pel), weight [B,R,1,H,W]
//         out  [B,C,H,W]
// B=4, R=2, C=19, H=256, W=512

#define Bv 4
#define Rv 2
#define Cv 19
#define Hv 256
#define Wv 512
#define HW (Hv * Wv)

__global__ __launch_bounds__(256)
void mc_warp_kernel(const float* __restrict__ pred,
                    const float* __restrict__ mv,
                    const float* __restrict__ wgt,
                    float* __restrict__ out)
{
    int idx = blockIdx.x * blockDim.x + threadIdx.x;   // 0 .. B*H*W-1
    int pix = idx & (HW - 1);          // HW = 131072, power of two
    int b   = idx >> 17;               // idx / HW
    int y   = pix >> 9;                // pix / W  (W=512)
    int x   = pix & (Wv - 1);

    float acc[Cv];
#pragma unroll
    for (int c = 0; c < Cv; ++c) acc[c] = 0.0f;

#pragma unroll
    for (int r = 0; r < Rv; ++r) {
        const int nr = b * Rv + r;
        const float* mvp = mv + (size_t)(nr * 2) * HW;
        float mvx = mvp[pix] * 0.25f;
        float mvy = mvp[HW + pix] * 0.25f;
        float w   = wgt[(size_t)nr * HW + pix];

        float gx = (float)x + mvx;
        float gy = (float)y + mvy;
        float x0f = floorf(gx);
        float y0f = floorf(gy);
        float wx1 = gx - x0f, wx0 = 1.0f - wx1;
        float wy1 = gy - y0f, wy0 = 1.0f - wy1;

        int x0 = (int)x0f;
        int y0 = (int)y0f;
        int x1 = x0 + 1;
        int y1 = y0 + 1;

        // validity (match reference: [0, dim-1] inclusive)
        float vx0 = (x0 >= 0 && x0 <= Wv - 1) ? 1.0f : 0.0f;
        float vx1 = (x1 >= 0 && x1 <= Wv - 1) ? 1.0f : 0.0f;
        float vy0 = (y0 >= 0 && y0 <= Hv - 1) ? 1.0f : 0.0f;
        float vy1 = (y1 >= 0 && y1 <= Hv - 1) ? 1.0f : 0.0f;

        // clamped indices (safe loads)
        int cx0 = min(max(x0, 0), Wv - 1);
        int cx1 = min(max(x1, 0), Wv - 1);
        int cy0 = min(max(y0, 0), Hv - 1);
        int cy1 = min(max(y1, 0), Hv - 1);

        float w00 = wy0 * wx0 * w * (vy0 * vx0);
        float w01 = wy0 * wx1 * w * (vy0 * vx1);
        float w10 = wy1 * wx0 * w * (vy1 * vx0);
        float w11 = wy1 * wx1 * w * (vy1 * vx1);

        int l00 = cy0 * Wv + cx0;
        int l01 = cy0 * Wv + cx1;
        int l10 = cy1 * Wv + cx0;
        int l11 = cy1 * Wv + cx1;

        const float* p = pred + (size_t)nr * Cv * HW;
#pragma unroll
        for (int c = 0; c < Cv; ++c) {
            float s00 = __ldg(p + l00);
            float s01 = __ldg(p + l01);
            float s10 = __ldg(p + l10);
            float s11 = __ldg(p + l11);
            acc[c] = fmaf(w00, s00,
                     fmaf(w01, s01,
                     fmaf(w10, s10,
                     fmaf(w11, s11, acc[c]))));
            p += HW;
        }
    }

    float* o = out + (size_t)b * Cv * HW + pix;
#pragma unroll
    for (int c = 0; c < Cv; ++c) {
        o[(size_t)c * HW] = acc[c];
    }
}

extern "C" void kernel_launch(void* const* d_in, const int* in_sizes, int n_in,
                              void* d_out, int out_size)
{
    const float* pred = (const float*)d_in[0];
    const float* mv   = (const float*)d_in[1];
    const float* wgt  = (const float*)d_in[2];
    float* out        = (float*)d_out;

    const int total = Bv * HW;                 // 524288 threads
    const int threads = 256;
    const int blocks = total / threads;        // 2048
    mc_warp_kernel<<<blocks, threads>>>(pred, mv, wgt, out);
}